// round 14
// baseline (speedup 1.0000x reference)
#include <cuda_runtime.h>
#include <cuda_bf16.h>
#include <math.h>
#include <stdint.h>

// ---------------- problem constants ----------------
#define BSZ    1024
#define NNODE  80
#define LMIR   30
#define LTGT   50
#define NDIM   256
#define FDIM   512
#define HEADS  4
#define CDIM   128
#define OUTD   128
#define MROWS  (BSZ*NNODE)       // 81920
#define LN_EPS 1e-5f

// int8 GEMM tiling: CTA 128x64, 8 warps (4M x 2N), warp tile 32x32, stage K=32
#define BM 128
#define BN 64
#define KSTG 32
#define NSTG 8
#define STG_BYTES 12288                 // Aq1 4K + Aq2 4K + Bq1 2K + Bq2 2K
#define GEMM_SMEM (NSTG*STG_BYTES)      // 96KB -> 2 CTAs/SM

// ---------------- device scratch ----------------
__device__ int8_t g_aq1 [(size_t)MROWS*FDIM];
__device__ int8_t g_aq2 [(size_t)MROWS*FDIM];
__device__ float  g_as  [(size_t)MROWS];
__device__ int8_t g_wiq1[(size_t)FDIM*NDIM];       // in_W^T quant [N=512,K=256]
__device__ int8_t g_wiq2[(size_t)FDIM*NDIM];
__device__ float  g_wis [(size_t)FDIM];
__device__ int8_t g_wcq1[(size_t)2*1024*FDIM];     // concat(Wl,Wr)^T per layer [N=1024,K=512]
__device__ int8_t g_wcq2[(size_t)2*1024*FDIM];
__device__ float  g_wcs [(size_t)2*1024];
__device__ float  g_bcat[(size_t)2*1024];
__device__ float  g_x   [(size_t)MROWS*FDIM];
__device__ float  g_xlr [(size_t)MROWS*1024];      // [xl | xr]
__device__ float  g_h   [(size_t)MROWS*FDIM];      // in-proj GEMM out only
__device__ float  g_pool[(size_t)BSZ*2*FDIM];
__device__ float  g_o   [(size_t)BSZ*OUTD];

// ---------------- PTX helpers ----------------
__device__ __forceinline__ uint32_t smem_u32(const void* p) {
    uint32_t a;
    asm("{ .reg .u64 t; cvta.to.shared.u64 t, %1; cvt.u32.u64 %0, t; }" : "=r"(a) : "l"(p));
    return a;
}
__device__ __forceinline__ void cp16(uint32_t saddr, const void* gaddr) {
    asm volatile("cp.async.cg.shared.global [%0], [%1], 16;" :: "r"(saddr), "l"(gaddr));
}
#define CP_COMMIT() asm volatile("cp.async.commit_group;" ::: "memory")

// swizzle for 32B rows: 16B-chunk bit (4) ^= row bit2 (bit 7) -> conflict-free LDSM
__device__ __forceinline__ uint32_t swz32(uint32_t off) { return off ^ ((off >> 3) & 0x10); }

#define LDMX4(r0,r1,r2,r3,a) \
    asm volatile("ldmatrix.sync.aligned.m8n8.x4.shared.b16 {%0,%1,%2,%3}, [%4];" \
        : "=r"(r0), "=r"(r1), "=r"(r2), "=r"(r3) : "r"(a))

#define IMMA(c, a, b0, b1) \
    asm volatile("mma.sync.aligned.m16n8k32.row.col.s32.s8.s8.s32 " \
        "{%0,%1,%2,%3}, {%4,%5,%6,%7}, {%8,%9}, {%0,%1,%2,%3};" \
        : "+r"((c)[0]), "+r"((c)[1]), "+r"((c)[2]), "+r"((c)[3]) \
        : "r"((a)[0]), "r"((a)[1]), "r"((a)[2]), "r"((a)[3]), "r"(b0), "r"(b1))

// ---------------- quantization helpers ----------------
// x ~= s*(q1 + q2/254), s = rowmax/127, q1,q2 in [-127,127]
__device__ __forceinline__ void quant2(float v, float inv127, int& q1, int& q2) {
    float a = v * inv127;
    float f1 = rintf(a);
    q1 = (int)f1;
    q2 = (int)rintf((a - f1) * 254.f);
}
__device__ __forceinline__ uint32_t pack4(int a, int b, int c, int d) {
    return (uint32_t)(a & 255) | ((uint32_t)(b & 255) << 8) |
           ((uint32_t)(c & 255) << 16) | ((uint32_t)(d & 255) << 24);
}
__device__ __forceinline__ float warp_max(float m) {
    #pragma unroll
    for (int o = 16; o; o >>= 1) m = fmaxf(m, __shfl_xor_sync(0xffffffffu, m, o));
    return m;
}

// ---------------- weight prep: per-column quantize (warp per column) ----------------
__global__ void prep_weights(const float* __restrict__ in_W,
                             const float* __restrict__ Wl, const float* __restrict__ Wr,
                             const float* __restrict__ bl, const float* __restrict__ br) {
    int gw = (blockIdx.x * blockDim.x + threadIdx.x) >> 5;
    int lane = threadIdx.x & 31;
    if (gw < FDIM) {
        int n = gw;
        float v[8];
        float m = 0.f;
        #pragma unroll
        for (int j = 0; j < 8; j++) {
            v[j] = in_W[(size_t)(lane*8 + j) * FDIM + n];
            m = fmaxf(m, fabsf(v[j]));
        }
        m = fmaxf(warp_max(m), 1e-20f);
        if (lane == 0) g_wis[n] = m * (1.f/127.f);
        float inv = 127.f / m;
        int q1[8], q2[8];
        #pragma unroll
        for (int j = 0; j < 8; j++) quant2(v[j], inv, q1[j], q2[j]);
        *(uint2*)(g_wiq1 + (size_t)n*NDIM + lane*8) =
            make_uint2(pack4(q1[0],q1[1],q1[2],q1[3]), pack4(q1[4],q1[5],q1[6],q1[7]));
        *(uint2*)(g_wiq2 + (size_t)n*NDIM + lane*8) =
            make_uint2(pack4(q2[0],q2[1],q2[2],q2[3]), pack4(q2[4],q2[5],q2[6],q2[7]));
        return;
    }
    int w2 = gw - FDIM;
    if (w2 < 2*1024) {
        int i = w2 >> 10, n = w2 & 1023;
        float v[16];
        float m = 0.f;
        #pragma unroll
        for (int j = 0; j < 16; j++) {
            int k = lane*16 + j;
            float val = (n < FDIM) ? Wl[(size_t)i*FDIM*FDIM + (size_t)k*FDIM + n]
                                   : Wr[(size_t)i*FDIM*FDIM + (size_t)k*FDIM + (n - FDIM)];
            v[j] = val;
            m = fmaxf(m, fabsf(val));
        }
        m = fmaxf(warp_max(m), 1e-20f);
        if (lane == 0) {
            g_wcs[i*1024 + n] = m * (1.f/127.f);
            g_bcat[i*1024 + n] = (n < FDIM) ? bl[i*FDIM + n] : br[i*FDIM + (n - FDIM)];
        }
        float inv = 127.f / m;
        int q1[16], q2[16];
        #pragma unroll
        for (int j = 0; j < 16; j++) quant2(v[j], inv, q1[j], q2[j]);
        size_t off = (size_t)(i*1024 + n) * FDIM + lane*16;
        *(uint4*)(g_wcq1 + off) = make_uint4(pack4(q1[0],q1[1],q1[2],q1[3]),   pack4(q1[4],q1[5],q1[6],q1[7]),
                                             pack4(q1[8],q1[9],q1[10],q1[11]), pack4(q1[12],q1[13],q1[14],q1[15]));
        *(uint4*)(g_wcq2 + off) = make_uint4(pack4(q2[0],q2[1],q2[2],q2[3]),   pack4(q2[4],q2[5],q2[6],q2[7]),
                                             pack4(q2[8],q2[9],q2[10],q2[11]), pack4(q2[12],q2[13],q2[14],q2[15]));
    }
}

// ---------------- build x0: concat + node emb, quantize rows (warp per row) ----------------
__global__ void build_x0(const float* __restrict__ mirna,
                         const float* __restrict__ target,
                         const float* __restrict__ ntype) {
    int row = (blockIdx.x * blockDim.x + threadIdx.x) >> 5;
    if (row >= MROWS) return;
    int lane = threadIdx.x & 31;
    int b = row / NNODE, v = row % NNODE;
    const float* src; const float* emb;
    if (v < LMIR) { src = mirna  + ((size_t)b*LMIR + v) * NDIM;        emb = ntype; }
    else          { src = target + ((size_t)b*LTGT + (v-LMIR)) * NDIM; emb = ntype + NDIM; }
    float vals[8];
    float m = 0.f;
    #pragma unroll
    for (int h = 0; h < 2; h++) {
        float4 a = *(const float4*)(src + lane*8 + h*4);
        float4 e = *(const float4*)(emb + lane*8 + h*4);
        vals[h*4+0] = a.x+e.x; vals[h*4+1] = a.y+e.y; vals[h*4+2] = a.z+e.z; vals[h*4+3] = a.w+e.w;
    }
    #pragma unroll
    for (int j = 0; j < 8; j++) m = fmaxf(m, fabsf(vals[j]));
    m = fmaxf(warp_max(m), 1e-20f);
    if (lane == 0) g_as[row] = m * (1.f/127.f);
    float inv = 127.f / m;
    int q1[8], q2[8];
    #pragma unroll
    for (int j = 0; j < 8; j++) quant2(vals[j], inv, q1[j], q2[j]);
    *(uint2*)(g_aq1 + (size_t)row*NDIM + lane*8) =
        make_uint2(pack4(q1[0],q1[1],q1[2],q1[3]), pack4(q1[4],q1[5],q1[6],q1[7]));
    *(uint2*)(g_aq2 + (size_t)row*NDIM + lane*8) =
        make_uint2(pack4(q2[0],q2[1],q2[2],q2[3]), pack4(q2[4],q2[5],q2[6],q2[7]));
}

// ---------------- int8 split GEMM: C = A@B^T + bias ----------------
// CTA 128x64, 8 warps (4M x 2N), warp tile 32x32; 2 CTAs/SM; depth-6 cp.async prefetch (K=32 stages).
__global__ __launch_bounds__(256, 2) void gemm_i8(
    const int8_t* __restrict__ Aq1, const int8_t* __restrict__ Aq2, const float* __restrict__ sa,
    const int8_t* __restrict__ Bq1, const int8_t* __restrict__ Bq2, const float* __restrict__ sb,
    const float* __restrict__ bias, float* __restrict__ C, int K, int N)
{
    extern __shared__ char sm[];
    const uint32_t smem_base = smem_u32(sm);
    const int tid = threadIdx.x;
    const int wid = tid >> 5, lane = tid & 31;
    const int m0 = blockIdx.y * BM;
    const int n0 = blockIdx.x * BN;
    const int nchunk = K >> 5;              // K per stage = 32
    const int warpM = (wid & 3) * 32;
    const int warpN = (wid >> 2) * 32;
    const int quad = lane >> 3, qr = lane & 7;

    int acc1[2][4][4], acc2[2][4][4];
    #pragma unroll
    for (int i = 0; i < 2; i++)
        #pragma unroll
        for (int j = 0; j < 4; j++)
            #pragma unroll
            for (int q = 0; q < 4; q++) { acc1[i][j][q] = 0; acc2[i][j][q] = 0; }

    const int8_t* Abase[2] = { Aq1 + (size_t)m0 * K, Aq2 + (size_t)m0 * K };
    const int8_t* Bbase[2] = { Bq1 + (size_t)n0 * K, Bq2 + (size_t)n0 * K };

    // stage layout: [Aq1 4K][Aq2 4K][Bq1 2K][Bq2 2K]; rows are 32B, swz32
    auto load_stage = [&](int slot, int c) {
        const uint32_t sb_ = smem_base + slot * STG_BYTES;
        const int k0 = c * KSTG;
        #pragma unroll
        for (int i = 0; i < 3; i++) {
            int idx = tid + i * 256;              // 0..767
            if (idx < 512) {                       // A: 2 x 256 16B-chunks
                int sub = idx >> 8, w = idx & 255;
                int row = w >> 1, ch = w & 1;
                cp16(sb_ + (sub << 12) + swz32((row << 5) + (ch << 4)),
                     Abase[sub] + (size_t)row * K + k0 + ch * 16);
            } else {                               // B: 2 x 128 16B-chunks
                int w = idx - 512;
                int sub = w >> 7; w &= 127;
                int row = w >> 1, ch = w & 1;
                cp16(sb_ + 8192 + (sub << 11) + swz32((row << 5) + (ch << 4)),
                     Bbase[sub] + (size_t)row * K + k0 + ch * 16);
            }
        }
        CP_COMMIT();
    };

    // preload up to NSTG-1 stages
    const int npre = (nchunk < NSTG-1) ? nchunk : (NSTG-1);
    for (int s = 0; s < npre; ++s) load_stage(s, s);

    for (int c = 0; c < nchunk; ++c) {
        int pend = nchunk - c - 1;
        if (pend > NSTG-2) pend = NSTG-2;          // groups committed beyond stage c
        switch (pend) {
            case 6: asm volatile("cp.async.wait_group 6;" ::: "memory"); break;
            case 5: asm volatile("cp.async.wait_group 5;" ::: "memory"); break;
            case 4: asm volatile("cp.async.wait_group 4;" ::: "memory"); break;
            case 3: asm volatile("cp.async.wait_group 3;" ::: "memory"); break;
            case 2: asm volatile("cp.async.wait_group 2;" ::: "memory"); break;
            case 1: asm volatile("cp.async.wait_group 1;" ::: "memory"); break;
            default: asm volatile("cp.async.wait_group 0;" ::: "memory"); break;
        }
        __syncthreads();
        if (c + NSTG-1 < nchunk) load_stage((c + NSTG-1) % NSTG, c + NSTG-1);

        const uint32_t sb_ = smem_base + (c % NSTG) * STG_BYTES;
        const int kb = (quad >> 1) * 16;
        uint32_t bq1f[2][4], bq2f[2][4];
        #pragma unroll
        for (int g = 0; g < 2; ++g) {
            int nrow = warpN + g*16 + (quad & 1)*8 + qr;
            uint32_t off = swz32((nrow << 5) + kb);
            LDMX4(bq1f[g][0], bq1f[g][1], bq1f[g][2], bq1f[g][3], sb_ + 8192 + off);
            LDMX4(bq2f[g][0], bq2f[g][1], bq2f[g][2], bq2f[g][3], sb_ + 10240 + off);
        }
        #pragma unroll
        for (int mt = 0; mt < 2; ++mt) {
            int arow = warpM + mt*16 + (quad & 1)*8 + qr;
            uint32_t off = swz32((arow << 5) + kb);
            uint32_t aq1f[4], aq2f[4];
            LDMX4(aq1f[0], aq1f[1], aq1f[2], aq1f[3], sb_ + off);
            LDMX4(aq2f[0], aq2f[1], aq2f[2], aq2f[3], sb_ + 4096 + off);
            #pragma unroll
            for (int ng = 0; ng < 4; ++ng) {
                IMMA(acc1[mt][ng], aq1f, bq1f[ng>>1][ng&1], bq1f[ng>>1][2+(ng&1)]);
                IMMA(acc2[mt][ng], aq1f, bq2f[ng>>1][ng&1], bq2f[ng>>1][2+(ng&1)]);
            }
            #pragma unroll
            for (int ng = 0; ng < 4; ++ng)
                IMMA(acc2[mt][ng], aq2f, bq1f[ng>>1][ng&1], bq1f[ng>>1][2+(ng&1)]);
        }
    }

    const float INV254 = 1.f/254.f;
    const int r = lane >> 2, c2 = (lane & 3) * 2;
    #pragma unroll
    for (int mt = 0; mt < 2; ++mt) {
        int row0 = m0 + warpM + mt*16 + r;
        float sa0 = sa[row0], sa1 = sa[row0 + 8];
        #pragma unroll
        for (int ng = 0; ng < 4; ++ng) {
            int col = n0 + warpN + ng*8 + c2;
            float sb0 = sb[col], sb1 = sb[col+1];
            float bx = bias[col], by = bias[col+1];
            float2 v0, v1;
            v0.x = sa0*sb0*((float)acc1[mt][ng][0] + (float)acc2[mt][ng][0]*INV254) + bx;
            v0.y = sa0*sb1*((float)acc1[mt][ng][1] + (float)acc2[mt][ng][1]*INV254) + by;
            v1.x = sa1*sb0*((float)acc1[mt][ng][2] + (float)acc2[mt][ng][2]*INV254) + bx;
            v1.y = sa1*sb1*((float)acc1[mt][ng][3] + (float)acc2[mt][ng][3]*INV254) + by;
            *(float2*)&C[(size_t)row0 * N + col]       = v0;
            *(float2*)&C[(size_t)(row0 + 8) * N + col] = v1;
        }
    }
}

// ---------------- warp-per-row LayerNorm + GELU (+ optional quant out) ----------------
__global__ void ln_gelu(const float* __restrict__ in, float* __restrict__ out,
                        int8_t* q1p, int8_t* q2p, float* sap,
                        const float* __restrict__ g, const float* __restrict__ b,
                        int rows, int width, int dogelu)
{
    int row = (blockIdx.x * blockDim.x + threadIdx.x) >> 5;
    if (row >= rows) return;
    int lane = threadIdx.x & 31;
    const float* rp = in + (size_t)row * width;
    int nv = width >> 7;
    float vals[16];
    float s = 0.f, ss = 0.f;
    for (int i = 0; i < nv; i++) {
        float4 v = *(const float4*)(rp + lane*4 + i*128);
        vals[i*4+0]=v.x; vals[i*4+1]=v.y; vals[i*4+2]=v.z; vals[i*4+3]=v.w;
        s  += v.x + v.y + v.z + v.w;
        ss += v.x*v.x + v.y*v.y + v.z*v.z + v.w*v.w;
    }
    #pragma unroll
    for (int o = 16; o; o >>= 1) {
        s  += __shfl_xor_sync(0xffffffffu, s,  o);
        ss += __shfl_xor_sync(0xffffffffu, ss, o);
    }
    float inv_w = 1.f / (float)width;
    float mu = s * inv_w;
    float var = ss * inv_w - mu * mu;
    float rr = rsqrtf(var + LN_EPS);
    float* op = out + (size_t)row * width;
    float m = 0.f;
    for (int i = 0; i < nv; i++) {
        int f = lane*4 + i*128;
        float4 gg = *(const float4*)(g + f);
        float4 bb = *(const float4*)(b + f);
        float y0 = (vals[i*4+0]-mu)*rr*gg.x + bb.x;
        float y1 = (vals[i*4+1]-mu)*rr*gg.y + bb.y;
        float y2 = (vals[i*4+2]-mu)*rr*gg.z + bb.z;
        float y3 = (vals[i*4+3]-mu)*rr*gg.w + bb.w;
        if (dogelu) {
            y0 = 0.5f*y0*(1.f+erff(y0*0.70710678118654752f));
            y1 = 0.5f*y1*(1.f+erff(y1*0.70710678118654752f));
            y2 = 0.5f*y2*(1.f+erff(y2*0.70710678118654752f));
            y3 = 0.5f*y3*(1.f+erff(y3*0.70710678118654752f));
        }
        vals[i*4+0]=y0; vals[i*4+1]=y1; vals[i*4+2]=y2; vals[i*4+3]=y3;
        m = fmaxf(fmaxf(fmaxf(fabsf(y0), fabsf(y1)), fmaxf(fabsf(y2), fabsf(y3))), m);
        *(float4*)(op + f) = make_float4(y0, y1, y2, y3);
    }
    if (q1p) {
        m = fmaxf(warp_max(m), 1e-20f);
        if (lane == 0) sap[row] = m * (1.f/127.f);
        float inv = 127.f / m;
        for (int i = 0; i < nv; i++) {
            int q1[4], q2[4];
            #pragma unroll
            for (int j = 0; j < 4; j++) quant2(vals[i*4+j], inv, q1[j], q2[j]);
            uint32_t* d1 = (uint32_t*)(q1p + (size_t)row*width) + i*32 + lane;
            uint32_t* d2 = (uint32_t*)(q2p + (size_t)row*width) + i*32 + lane;
            *d1 = pack4(q1[0],q1[1],q1[2],q1[3]);
            *d2 = pack4(q2[0],q2[1],q2[2],q2[3]);
        }
    }
}

// ---------------- fused GAT + residual-LN, warp per node ----------------
__global__ __launch_bounds__(256) void gat_ln(
    const float* __restrict__ xlr,
    const float* __restrict__ etype_emb,   // [3,4]
    const float* __restrict__ We,          // [4,512]
    const float* __restrict__ att,         // [4,128] = [512]
    const float* __restrict__ bo,          // [512]
    const float* __restrict__ lng, const float* __restrict__ lnb,
    float* __restrict__ x,
    int8_t* q1p, int8_t* q2p, float* sap,
    int dogelu_quant)
{
    int row = (blockIdx.x * blockDim.x + threadIdx.x) >> 5;
    if (row >= MROWS) return;
    const int lane = threadIdx.x & 31;
    const int b = row / NNODE, v = row % NNODE;

    float at[16], e0[16], e2[16], xrv[16];
    const float et0[4] = { etype_emb[0], etype_emb[1], etype_emb[2], etype_emb[3] };
    const float et2[4] = { etype_emb[8], etype_emb[9], etype_emb[10], etype_emb[11] };
    const float* xrow = xlr + (size_t)row * 1024;
    #pragma unroll
    for (int i = 0; i < 4; i++) {
        int f = lane*4 + i*128;
        float4 a4 = *(const float4*)(att + f);
        at[i*4+0]=a4.x; at[i*4+1]=a4.y; at[i*4+2]=a4.z; at[i*4+3]=a4.w;
        float4 w0 = *(const float4*)(We + 0*FDIM + f);
        float4 w1 = *(const float4*)(We + 1*FDIM + f);
        float4 w2 = *(const float4*)(We + 2*FDIM + f);
        float4 w3 = *(const float4*)(We + 3*FDIM + f);
        e0[i*4+0] = et0[0]*w0.x + et0[1]*w1.x + et0[2]*w2.x + et0[3]*w3.x;
        e0[i*4+1] = et0[0]*w0.y + et0[1]*w1.y + et0[2]*w2.y + et0[3]*w3.y;
        e0[i*4+2] = et0[0]*w0.z + et0[1]*w1.z + et0[2]*w2.z + et0[3]*w3.z;
        e0[i*4+3] = et0[0]*w0.w + et0[1]*w1.w + et0[2]*w2.w + et0[3]*w3.w;
        e2[i*4+0] = et2[0]*w0.x + et2[1]*w1.x + et2[2]*w2.x + et2[3]*w3.x;
        e2[i*4+1] = et2[0]*w0.y + et2[1]*w1.y + et2[2]*w2.y + et2[3]*w3.y;
        e2[i*4+2] = et2[0]*w0.z + et2[1]*w1.z + et2[2]*w2.z + et2[3]*w3.z;
        e2[i*4+3] = et2[0]*w0.w + et2[1]*w1.w + et2[2]*w2.w + et2[3]*w3.w;
        float4 xr4 = *(const float4*)(xrow + FDIM + f);
        xrv[i*4+0]=xr4.x; xrv[i*4+1]=xr4.y; xrv[i*4+2]=xr4.z; xrv[i*4+3]=xr4.w;
    }

    const int lo = (v < LMIR) ? 0 : LMIR;
    const int hi = (v < LMIR) ? (LMIR-1) : (NNODE-1);
    int   srcs[5];
    float c0[5], c2c[5], valid[5];
    srcs[0]=v-1; srcs[1]=v+1; srcs[2]=v-2; srcs[3]=v+2; srcs[4]=v;
    valid[0] = (v-1 >= lo) ? 1.f : 0.f;
    valid[1] = (v+1 <= hi) ? 1.f : 0.f;
    valid[2] = (v-2 >= lo) ? 1.f : 0.f;
    valid[3] = (v+2 <= hi) ? 1.f : 0.f;
    valid[4] = 1.f;
    c0[0]=1.f; c2c[0]=0.f;  c0[1]=1.f; c2c[1]=0.f;
    c0[2]=0.f; c2c[2]=1.f;  c0[3]=0.f; c2c[3]=1.f;
    float n0 = valid[0] + valid[1];
    float n2 = valid[2] + valid[3];
    float invn = 1.f / (n0 + n2);
    c0[4] = n0 * invn; c2c[4] = n2 * invn;
    #pragma unroll
    for (int e = 0; e < 5; e++) {
        int s = srcs[e];
        s = s < 0 ? 0 : (s > NNODE-1 ? NNODE-1 : s);
        srcs[e] = s;
    }

    float a[5][4];
    #pragma unroll
    for (int e = 0; e < 5; e++) {
        const float* xs = xlr + ((size_t)(b*NNODE) + srcs[e]) * 1024;
        float p0=0.f, p1=0.f, p2=0.f, p3=0.f;
        #pragma unroll
        for (int i = 0; i < 4; i++) {
            int f = lane*4 + i*128;
            float4 xv = *(const float4*)(xs + f);
            float mv[4] = {xv.x, xv.y, xv.z, xv.w};
            float p = 0.f;
            #pragma unroll
            for (int j = 0; j < 4; j++) {
                float mm = mv[j] + xrv[i*4+j] + c0[e]*e0[i*4+j] + c2c[e]*e2[i*4+j];
                mm = (mm > 0.f) ? mm : 0.2f*mm;
                p += mm * at[i*4+j];
            }
            if (i == 0) p0 = p; else if (i == 1) p1 = p; else if (i == 2) p2 = p; else p3 = p;
        }
        #pragma unroll
        for (int o = 16; o; o >>= 1) {
            p0 += __shfl_xor_sync(0xffffffffu, p0, o);
            p1 += __shfl_xor_sync(0xffffffffu, p1, o);
            p2 += __shfl_xor_sync(0xffffffffu, p2, o);
            p3 += __shfl_xor_sync(0xffffffffu, p3, o);
        }
        a[e][0] = (valid[e] > 0.f) ? p0 : -1e30f;
        a[e][1] = (valid[e] > 0.f) ? p1 : -1e30f;
        a[e][2] = (valid[e] > 0.f) ? p2 : -1e30f;
        a[e][3] = (valid[e] > 0.f) ? p3 : -1e30f;
    }
    #pragma unroll
    for (int h = 0; h < 4; h++) {
        float amax = a[0][h];
        #pragma unroll
        for (int e = 1; e < 5; e++) amax = fmaxf(amax, a[e][h]);
        float den = 0.f;
        #pragma unroll
        for (int e = 0; e < 5; e++) { a[e][h] = expf(a[e][h] - amax); den += a[e][h]; }
        float invd = 1.f / den;
        #pragma unroll
        for (int e = 0; e < 5; e++) a[e][h] *= invd;
    }

    float vals[16];
    float* xp = x + (size_t)row * FDIM;
    #pragma unroll
    for (int i = 0; i < 4; i++) {
        int f = lane*4 + i*128;
        float4 bv = *(const float4*)(bo + f);
        float4 xv = *(const float4*)(xp + f);
        vals[i*4+0] = bv.x + xv.x; vals[i*4+1] = bv.y + xv.y;
        vals[i*4+2] = bv.z + xv.z; vals[i*4+3] = bv.w + xv.w;
    }
    #pragma unroll
    for (int e = 0; e < 5; e++) {
        const float* xs = xlr + ((size_t)(b*NNODE) + srcs[e]) * 1024;
        #pragma unroll
        for (int i = 0; i < 4; i++) {
            int f = lane*4 + i*128;
            float4 xv = *(const float4*)(xs + f);
            float al = a[e][i];
            vals[i*4+0] += al * xv.x; vals[i*4+1] += al * xv.y;
            vals[i*4+2] += al * xv.z; vals[i*4+3] += al * xv.w;
        }
    }
    float s = 0.f, ss = 0.f;
    #pragma unroll
    for (int j = 0; j < 16; j++) { s += vals[j]; ss += vals[j]*vals[j]; }
    #pragma unroll
    for (int o = 16; o; o >>= 1) {
        s  += __shfl_xor_sync(0xffffffffu, s,  o);
        ss += __shfl_xor_sync(0xffffffffu, ss, o);
    }
    float mu = s * (1.f/FDIM);
    float var = ss * (1.f/FDIM) - mu*mu;
    float rr = rsqrtf(var + LN_EPS);
    float m = 0.f;
    #pragma unroll
    for (int i = 0; i < 4; i++) {
        int f = lane*4 + i*128;
        float4 gg = *(const float4*)(lng + f);
        float4 bb = *(const float4*)(lnb + f);
        float y0 = (vals[i*4+0]-mu)*rr*gg.x + bb.x;
        float y1 = (vals[i*4+1]-mu)*rr*gg.y + bb.y;
        float y2 = (vals[i*4+2]-mu)*rr*gg.z + bb.z;
        float y3 = (vals[i*4+3]-mu)*rr*gg.w + bb.w;
        if (dogelu_quant) {
            y0 = 0.5f*y0*(1.f+erff(y0*0.70710678118654752f));
            y1 = 0.5f*y1*(1.f+erff(y1*0.70710678118654752f));
            y2 = 0.5f*y2*(1.f+erff(y2*0.70710678118654752f));
            y3 = 0.5f*y3*(1.f+erff(y3*0.70710678118654752f));
        }
        vals[i*4+0]=y0; vals[i*4+1]=y1; vals[i*4+2]=y2; vals[i*4+3]=y3;
        m = fmaxf(fmaxf(fmaxf(fabsf(y0), fabsf(y1)), fmaxf(fabsf(y2), fabsf(y3))), m);
        *(float4*)(xp + f) = make_float4(y0, y1, y2, y3);
    }
    if (dogelu_quant) {
        m = fmaxf(warp_max(m), 1e-20f);
        if (lane == 0) sap[row] = m * (1.f/127.f);
        float inv = 127.f / m;
        #pragma unroll
        for (int i = 0; i < 4; i++) {
            int q1[4], q2[4];
            #pragma unroll
            for (int j = 0; j < 4; j++) quant2(vals[i*4+j], inv, q1[j], q2[j]);
            uint32_t* d1 = (uint32_t*)(q1p + (size_t)row*FDIM) + i*32 + lane;
            uint32_t* d2 = (uint32_t*)(q2p + (size_t)row*FDIM) + i*32 + lane;
            *d1 = pack4(q1[0],q1[1],q1[2],q1[3]);
            *d2 = pack4(q2[0],q2[1],q2[2],q2[3]);
        }
    }
}

// ---------------- mean/max pool ----------------
__global__ void pool(const float* __restrict__ x, float* __restrict__ pooled) {
    int b = blockIdx.x;
    int f = threadIdx.x;
    const float* xp = x + (size_t)b * NNODE * FDIM + f;
    float s = 0.f, mx = -3.4e38f;
    #pragma unroll 4
    for (int v = 0; v < NNODE; v++) {
        float val = xp[(size_t)v * FDIM];
        s += val;
        mx = fmaxf(mx, val);
    }
    pooled[(size_t)b*2*FDIM + f]        = s * (1.f/NNODE);
    pooled[(size_t)b*2*FDIM + FDIM + f] = mx;
}

// ---------------- head GEMM (tiny, fp32) ----------------
__global__ __launch_bounds__(128) void gemm_out(
    const float* __restrict__ A, const float* __restrict__ Bw,
    const float* __restrict__ bias, float* __restrict__ C)
{
    __shared__ float As[8][1024];
    const int r0 = blockIdx.x * 8;
    const int tid = threadIdx.x;
    for (int i4 = tid; i4 < 8*1024/4; i4 += 128)
        *(float4*)(&As[0][0] + (size_t)i4*4) = *(const float4*)(A + (size_t)r0*1024 + (size_t)i4*4);
    __syncthreads();
    float acc[8];
    #pragma unroll
    for (int r = 0; r < 8; r++) acc[r] = 0.f;
    #pragma unroll 4
    for (int k = 0; k < 1024; k++) {
        float bv = Bw[(size_t)k*128 + tid];
        #pragma unroll
        for (int r = 0; r < 8; r++) acc[r] += As[r][k] * bv;
    }
    float bi = bias[tid];
    #pragma unroll
    for (int r = 0; r < 8; r++)
        C[(size_t)(r0 + r)*128 + tid] = acc[r] + bi;
}

// ---------------- launch ----------------
extern "C" void kernel_launch(void* const* d_in, const int* in_sizes, int n_in,
                              void* d_out, int out_size) {
    const float* mirna  = (const float*)d_in[0];
    const float* target = (const float*)d_in[1];
    const float* ntype  = (const float*)d_in[2];
    const float* etype  = (const float*)d_in[3];
    const float* in_W   = (const float*)d_in[4];
    const float* in_b   = (const float*)d_in[5];
    const float* in_lng = (const float*)d_in[6];
    const float* in_lnb = (const float*)d_in[7];
    const float* Wl     = (const float*)d_in[8];
    const float* bl     = (const float*)d_in[9];
    const float* Wr     = (const float*)d_in[10];
    const float* br     = (const float*)d_in[11];
    const float* We     = (const float*)d_in[12];
    const float* attw   = (const float*)d_in[13];
    const float* bo     = (const float*)d_in[14];
    const float* lng    = (const float*)d_in[15];
    const float* lnb    = (const float*)d_in[16];
    const float* outW   = (const float*)d_in[17];
    const float* outb   = (const float*)d_in[18];
    const float* olng   = (const float*)d_in[19];
    const float* olnb   = (const float*)d_in[20];
    float* out = (float*)d_out;

    float *xp, *xlrp, *hp, *poolp, *op, *bcatp, *asp, *wisp, *wcsp;
    int8_t *aq1p, *aq2p, *wiq1p, *wiq2p, *wcq1p, *wcq2p;
    cudaGetSymbolAddress((void**)&aq1p,  g_aq1);
    cudaGetSymbolAddress((void**)&aq2p,  g_aq2);
    cudaGetSymbolAddress((void**)&asp,   g_as);
    cudaGetSymbolAddress((void**)&wiq1p, g_wiq1);
    cudaGetSymbolAddress((void**)&wiq2p, g_wiq2);
    cudaGetSymbolAddress((void**)&wisp,  g_wis);
    cudaGetSymbolAddress((void**)&wcq1p, g_wcq1);
    cudaGetSymbolAddress((void**)&wcq2p, g_wcq2);
    cudaGetSymbolAddress((void**)&wcsp,  g_wcs);
    cudaGetSymbolAddress((void**)&bcatp, g_bcat);
    cudaGetSymbolAddress((void**)&xp,    g_x);
    cudaGetSymbolAddress((void**)&xlrp,  g_xlr);
    cudaGetSymbolAddress((void**)&hp,    g_h);
    cudaGetSymbolAddress((void**)&poolp, g_pool);
    cudaGetSymbolAddress((void**)&op,    g_o);

    cudaFuncSetAttribute(gemm_i8, cudaFuncAttributeMaxDynamicSharedMemorySize, GEMM_SMEM);

    prep_weights<<<(2560*32 + 255)/256, 256>>>(in_W, Wl, Wr, bl, br);
    build_x0<<<(MROWS*32 + 255)/256, 256>>>(mirna, target, ntype);

    // input projection (M=81920, N=512, K=256)
    gemm_i8<<<dim3(FDIM/BN, MROWS/BM), 256, GEMM_SMEM>>>(
        aq1p, aq2p, asp, wiq1p, wiq2p, wisp, in_b, hp, NDIM, FDIM);
    ln_gelu<<<(MROWS*32 + 255)/256, 256>>>(hp, xp, aq1p, aq2p, asp,
                                           in_lng, in_lnb, MROWS, FDIM, 1);

    // GAT layers: fused [Wl|Wr] int8 GEMM + fused gat+resid_ln
    for (int i = 0; i < 2; i++) {
        gemm_i8<<<dim3(1024/BN, MROWS/BM), 256, GEMM_SMEM>>>(
            aq1p, aq2p, asp,
            wcq1p + (size_t)i*1024*FDIM, wcq2p + (size_t)i*1024*FDIM, wcsp + (size_t)i*1024,
            bcatp + (size_t)i*1024, xlrp, FDIM, 1024);
        gat_ln<<<(MROWS*32 + 255)/256, 256>>>(
            xlrp, etype,
            We + (size_t)i*HEADS*FDIM, attw + (size_t)i*HEADS*CDIM,
            bo + (size_t)i*FDIM, lng + (size_t)i*FDIM, lnb + (size_t)i*FDIM,
            xp, aq1p, aq2p, asp, (i == 0) ? 1 : 0);
    }

    // pool + head
    pool<<<BSZ, FDIM>>>(xp, poolp);
    gemm_out<<<BSZ/8, 128>>>(poolp, outW, outb, op);
    ln_gelu<<<(BSZ*32 + 255)/256, 256>>>(op, out, (int8_t*)nullptr, (int8_t*)nullptr, (float*)nullptr,
                                         olng, olnb, BSZ, OUTD, 1);
}

// round 15
// speedup vs baseline: 1.1767x; 1.1767x over previous
#include <cuda_runtime.h>
#include <cuda_bf16.h>
#include <math.h>
#include <stdint.h>

// ---------------- problem constants ----------------
#define BSZ    1024
#define NNODE  80
#define LMIR   30
#define LTGT   50
#define NDIM   256
#define FDIM   512
#define HEADS  4
#define CDIM   128
#define OUTD   128
#define MROWS  (BSZ*NNODE)       // 81920
#define LN_EPS 1e-5f

// int8 GEMM tiling: CTA 128x64, 8 warps (4 M x 2 N), warp tile 32x32, stage K=64
#define BM 128
#define BN 64
#define KSTG 64
#define NSTG 4
#define STG_BYTES 24576                 // Aq1 8K + Aq2 8K + Bq1 4K + Bq2 4K
#define GEMM_SMEM (NSTG*STG_BYTES)      // 96KB -> 2 CTAs/SM

// ---------------- device scratch ----------------
__device__ int8_t g_aq1 [(size_t)MROWS*FDIM];
__device__ int8_t g_aq2 [(size_t)MROWS*FDIM];
__device__ float  g_as  [(size_t)MROWS];
__device__ int8_t g_wiq1[(size_t)FDIM*NDIM];       // in_W^T quant [N=512,K=256]
__device__ int8_t g_wiq2[(size_t)FDIM*NDIM];
__device__ float  g_wis [(size_t)FDIM];
__device__ int8_t g_wcq1[(size_t)2*1024*FDIM];     // concat(Wl,Wr)^T per layer [N=1024,K=512]
__device__ int8_t g_wcq2[(size_t)2*1024*FDIM];
__device__ float  g_wcs [(size_t)2*1024];
__device__ float  g_bcat[(size_t)2*1024];
__device__ float  g_x   [(size_t)MROWS*FDIM];
__device__ float  g_xlr [(size_t)MROWS*1024];      // [xl | xr]
__device__ float  g_h   [(size_t)MROWS*FDIM];      // in-proj GEMM out only
__device__ float  g_pool[(size_t)BSZ*2*FDIM];
__device__ float  g_o   [(size_t)BSZ*OUTD];

// ---------------- PTX helpers ----------------
__device__ __forceinline__ uint32_t smem_u32(const void* p) {
    uint32_t a;
    asm("{ .reg .u64 t; cvta.to.shared.u64 t, %1; cvt.u32.u64 %0, t; }" : "=r"(a) : "l"(p));
    return a;
}
__device__ __forceinline__ void cp16(uint32_t saddr, const void* gaddr) {
    asm volatile("cp.async.cg.shared.global [%0], [%1], 16;" :: "r"(saddr), "l"(gaddr));
}
#define CP_COMMIT() asm volatile("cp.async.commit_group;" ::: "memory")

__device__ __forceinline__ uint32_t swz64(uint32_t off) { return off ^ ((off >> 3) & 0x30); }

#define LDMX4(r0,r1,r2,r3,a) \
    asm volatile("ldmatrix.sync.aligned.m8n8.x4.shared.b16 {%0,%1,%2,%3}, [%4];" \
        : "=r"(r0), "=r"(r1), "=r"(r2), "=r"(r3) : "r"(a))

#define IMMA(c, a, b0, b1) \
    asm volatile("mma.sync.aligned.m16n8k32.row.col.s32.s8.s8.s32 " \
        "{%0,%1,%2,%3}, {%4,%5,%6,%7}, {%8,%9}, {%0,%1,%2,%3};" \
        : "+r"((c)[0]), "+r"((c)[1]), "+r"((c)[2]), "+r"((c)[3]) \
        : "r"((a)[0]), "r"((a)[1]), "r"((a)[2]), "r"((a)[3]), "r"(b0), "r"(b1))

// ---------------- quantization helpers ----------------
// x ~= s*(q1 + q2/254), s = rowmax/127, q1,q2 in [-127,127]
__device__ __forceinline__ void quant2(float v, float inv127, int& q1, int& q2) {
    float a = v * inv127;
    float f1 = rintf(a);
    q1 = (int)f1;
    q2 = (int)rintf((a - f1) * 254.f);
}
__device__ __forceinline__ uint32_t pack4(int a, int b, int c, int d) {
    return (uint32_t)(a & 255) | ((uint32_t)(b & 255) << 8) |
           ((uint32_t)(c & 255) << 16) | ((uint32_t)(d & 255) << 24);
}
__device__ __forceinline__ float warp_max(float m) {
    #pragma unroll
    for (int o = 16; o; o >>= 1) m = fmaxf(m, __shfl_xor_sync(0xffffffffu, m, o));
    return m;
}

// ---------------- weight prep: per-column quantize (warp per column) ----------------
__global__ void prep_weights(const float* __restrict__ in_W,
                             const float* __restrict__ Wl, const float* __restrict__ Wr,
                             const float* __restrict__ bl, const float* __restrict__ br) {
    int gw = (blockIdx.x * blockDim.x + threadIdx.x) >> 5;
    int lane = threadIdx.x & 31;
    if (gw < FDIM) {
        int n = gw;
        float v[8];
        float m = 0.f;
        #pragma unroll
        for (int j = 0; j < 8; j++) {
            v[j] = in_W[(size_t)(lane*8 + j) * FDIM + n];
            m = fmaxf(m, fabsf(v[j]));
        }
        m = fmaxf(warp_max(m), 1e-20f);
        if (lane == 0) g_wis[n] = m * (1.f/127.f);
        float inv = 127.f / m;
        int q1[8], q2[8];
        #pragma unroll
        for (int j = 0; j < 8; j++) quant2(v[j], inv, q1[j], q2[j]);
        *(uint2*)(g_wiq1 + (size_t)n*NDIM + lane*8) =
            make_uint2(pack4(q1[0],q1[1],q1[2],q1[3]), pack4(q1[4],q1[5],q1[6],q1[7]));
        *(uint2*)(g_wiq2 + (size_t)n*NDIM + lane*8) =
            make_uint2(pack4(q2[0],q2[1],q2[2],q2[3]), pack4(q2[4],q2[5],q2[6],q2[7]));
        return;
    }
    int w2 = gw - FDIM;
    if (w2 < 2*1024) {
        int i = w2 >> 10, n = w2 & 1023;
        float v[16];
        float m = 0.f;
        #pragma unroll
        for (int j = 0; j < 16; j++) {
            int k = lane*16 + j;
            float val = (n < FDIM) ? Wl[(size_t)i*FDIM*FDIM + (size_t)k*FDIM + n]
                                   : Wr[(size_t)i*FDIM*FDIM + (size_t)k*FDIM + (n - FDIM)];
            v[j] = val;
            m = fmaxf(m, fabsf(val));
        }
        m = fmaxf(warp_max(m), 1e-20f);
        if (lane == 0) {
            g_wcs[i*1024 + n] = m * (1.f/127.f);
            g_bcat[i*1024 + n] = (n < FDIM) ? bl[i*FDIM + n] : br[i*FDIM + (n - FDIM)];
        }
        float inv = 127.f / m;
        int q1[16], q2[16];
        #pragma unroll
        for (int j = 0; j < 16; j++) quant2(v[j], inv, q1[j], q2[j]);
        size_t off = (size_t)(i*1024 + n) * FDIM + lane*16;
        *(uint4*)(g_wcq1 + off) = make_uint4(pack4(q1[0],q1[1],q1[2],q1[3]),   pack4(q1[4],q1[5],q1[6],q1[7]),
                                             pack4(q1[8],q1[9],q1[10],q1[11]), pack4(q1[12],q1[13],q1[14],q1[15]));
        *(uint4*)(g_wcq2 + off) = make_uint4(pack4(q2[0],q2[1],q2[2],q2[3]),   pack4(q2[4],q2[5],q2[6],q2[7]),
                                             pack4(q2[8],q2[9],q2[10],q2[11]), pack4(q2[12],q2[13],q2[14],q2[15]));
    }
}

// ---------------- build x0: concat + node emb, quantize rows (warp per row) ----------------
__global__ void build_x0(const float* __restrict__ mirna,
                         const float* __restrict__ target,
                         const float* __restrict__ ntype) {
    int row = (blockIdx.x * blockDim.x + threadIdx.x) >> 5;
    if (row >= MROWS) return;
    int lane = threadIdx.x & 31;
    int b = row / NNODE, v = row % NNODE;
    const float* src; const float* emb;
    if (v < LMIR) { src = mirna  + ((size_t)b*LMIR + v) * NDIM;        emb = ntype; }
    else          { src = target + ((size_t)b*LTGT + (v-LMIR)) * NDIM; emb = ntype + NDIM; }
    float vals[8];
    float m = 0.f;
    #pragma unroll
    for (int h = 0; h < 2; h++) {
        float4 a = *(const float4*)(src + lane*8 + h*4);
        float4 e = *(const float4*)(emb + lane*8 + h*4);
        vals[h*4+0] = a.x+e.x; vals[h*4+1] = a.y+e.y; vals[h*4+2] = a.z+e.z; vals[h*4+3] = a.w+e.w;
    }
    #pragma unroll
    for (int j = 0; j < 8; j++) m = fmaxf(m, fabsf(vals[j]));
    m = fmaxf(warp_max(m), 1e-20f);
    if (lane == 0) g_as[row] = m * (1.f/127.f);
    float inv = 127.f / m;
    int q1[8], q2[8];
    #pragma unroll
    for (int j = 0; j < 8; j++) quant2(vals[j], inv, q1[j], q2[j]);
    *(uint2*)(g_aq1 + (size_t)row*NDIM + lane*8) =
        make_uint2(pack4(q1[0],q1[1],q1[2],q1[3]), pack4(q1[4],q1[5],q1[6],q1[7]));
    *(uint2*)(g_aq2 + (size_t)row*NDIM + lane*8) =
        make_uint2(pack4(q2[0],q2[1],q2[2],q2[3]), pack4(q2[4],q2[5],q2[6],q2[7]));
}

// ---------------- int8 split GEMM: C = A@B^T + bias ----------------
// CTA 128x64, 8 warps (4M x 2N), warp tile 32x32; 2 CTAs/SM; depth-3 cp.async prefetch.
__global__ __launch_bounds__(256, 2) void gemm_i8(
    const int8_t* __restrict__ Aq1, const int8_t* __restrict__ Aq2, const float* __restrict__ sa,
    const int8_t* __restrict__ Bq1, const int8_t* __restrict__ Bq2, const float* __restrict__ sb,
    const float* __restrict__ bias, float* __restrict__ C, int K, int N)
{
    extern __shared__ char sm[];
    const uint32_t smem_base = smem_u32(sm);
    const int tid = threadIdx.x;
    const int wid = tid >> 5, lane = tid & 31;
    const int m0 = blockIdx.y * BM;
    const int n0 = blockIdx.x * BN;
    const int nchunk = K >> 6;
    const int warpM = (wid & 3) * 32;
    const int warpN = (wid >> 2) * 32;
    const int quad = lane >> 3, qr = lane & 7;

    int acc1[2][4][4], acc2[2][4][4];
    #pragma unroll
    for (int i = 0; i < 2; i++)
        #pragma unroll
        for (int j = 0; j < 4; j++)
            #pragma unroll
            for (int q = 0; q < 4; q++) { acc1[i][j][q] = 0; acc2[i][j][q] = 0; }

    const int8_t* Abase[2] = { Aq1 + (size_t)m0 * K, Aq2 + (size_t)m0 * K };
    const int8_t* Bbase[2] = { Bq1 + (size_t)n0 * K, Bq2 + (size_t)n0 * K };

    auto load_stage = [&](int slot, int c) {
        const uint32_t sb_ = smem_base + slot * STG_BYTES;
        const int k0 = c * KSTG;
        #pragma unroll
        for (int i = 0; i < 6; i++) {
            int idx = tid + i * 256;              // 0..1535
            if (idx < 1024) {
                int sub = idx >> 9, w = idx & 511;
                int row = w >> 2, ch = w & 3;
                cp16(sb_ + (sub << 13) + swz64((row << 6) + (ch << 4)),
                     Abase[sub] + (size_t)row * K + k0 + ch * 16);
            } else {
                int w = idx - 1024;
                int sub = w >> 8; w &= 255;
                int row = w >> 2, ch = w & 3;
                cp16(sb_ + 16384 + (sub << 12) + swz64((row << 6) + (ch << 4)),
                     Bbase[sub] + (size_t)row * K + k0 + ch * 16);
            }
        }
        CP_COMMIT();
    };

    // preload up to 3 stages
    load_stage(0, 0);
    if (nchunk > 1) load_stage(1, 1);
    if (nchunk > 2) load_stage(2, 2);

    for (int c = 0; c < nchunk; ++c) {
        int pend = nchunk - c - 1;                // outstanding groups beyond stage c
        if (pend >= 2)      asm volatile("cp.async.wait_group 2;" ::: "memory");
        else if (pend == 1) asm volatile("cp.async.wait_group 1;" ::: "memory");
        else                asm volatile("cp.async.wait_group 0;" ::: "memory");
        __syncthreads();
        if (c + 3 < nchunk) load_stage((c + 3) % NSTG, c + 3);

        const uint32_t sb_ = smem_base + (c % NSTG) * STG_BYTES;
        #pragma unroll
        for (int kc = 0; kc < 2; ++kc) {
            const int kb = kc*32 + (quad >> 1) * 16;
            uint32_t bq1f[2][4], bq2f[2][4];
            #pragma unroll
            for (int g = 0; g < 2; ++g) {
                int nrow = warpN + g*16 + (quad & 1)*8 + qr;
                uint32_t off = swz64((nrow << 6) + kb);
                LDMX4(bq1f[g][0], bq1f[g][1], bq1f[g][2], bq1f[g][3], sb_ + 16384 + off);
                LDMX4(bq2f[g][0], bq2f[g][1], bq2f[g][2], bq2f[g][3], sb_ + 20480 + off);
            }
            #pragma unroll
            for (int mt = 0; mt < 2; ++mt) {
                int arow = warpM + mt*16 + (quad & 1)*8 + qr;
                uint32_t off = swz64((arow << 6) + kb);
                uint32_t aq1f[4], aq2f[4];
                LDMX4(aq1f[0], aq1f[1], aq1f[2], aq1f[3], sb_ + off);
                LDMX4(aq2f[0], aq2f[1], aq2f[2], aq2f[3], sb_ + 8192 + off);
                #pragma unroll
                for (int ng = 0; ng < 4; ++ng) {
                    IMMA(acc1[mt][ng], aq1f, bq1f[ng>>1][ng&1], bq1f[ng>>1][2+(ng&1)]);
                    IMMA(acc2[mt][ng], aq1f, bq2f[ng>>1][ng&1], bq2f[ng>>1][2+(ng&1)]);
                }
                #pragma unroll
                for (int ng = 0; ng < 4; ++ng)
                    IMMA(acc2[mt][ng], aq2f, bq1f[ng>>1][ng&1], bq1f[ng>>1][2+(ng&1)]);
            }
        }
    }

    const float INV254 = 1.f/254.f;
    const int r = lane >> 2, c2 = (lane & 3) * 2;
    #pragma unroll
    for (int mt = 0; mt < 2; ++mt) {
        int row0 = m0 + warpM + mt*16 + r;
        float sa0 = sa[row0], sa1 = sa[row0 + 8];
        #pragma unroll
        for (int ng = 0; ng < 4; ++ng) {
            int col = n0 + warpN + ng*8 + c2;
            float sb0 = sb[col], sb1 = sb[col+1];
            float bx = bias[col], by = bias[col+1];
            float2 v0, v1;
            v0.x = sa0*sb0*((float)acc1[mt][ng][0] + (float)acc2[mt][ng][0]*INV254) + bx;
            v0.y = sa0*sb1*((float)acc1[mt][ng][1] + (float)acc2[mt][ng][1]*INV254) + by;
            v1.x = sa1*sb0*((float)acc1[mt][ng][2] + (float)acc2[mt][ng][2]*INV254) + bx;
            v1.y = sa1*sb1*((float)acc1[mt][ng][3] + (float)acc2[mt][ng][3]*INV254) + by;
            *(float2*)&C[(size_t)row0 * N + col]       = v0;
            *(float2*)&C[(size_t)(row0 + 8) * N + col] = v1;
        }
    }
}

// ---------------- warp-per-row LayerNorm + GELU (+ optional quant out) ----------------
__global__ void ln_gelu(const float* __restrict__ in, float* __restrict__ out,
                        int8_t* q1p, int8_t* q2p, float* sap,
                        const float* __restrict__ g, const float* __restrict__ b,
                        int rows, int width, int dogelu)
{
    int row = (blockIdx.x * blockDim.x + threadIdx.x) >> 5;
    if (row >= rows) return;
    int lane = threadIdx.x & 31;
    const float* rp = in + (size_t)row * width;
    int nv = width >> 7;
    float vals[16];
    float s = 0.f, ss = 0.f;
    for (int i = 0; i < nv; i++) {
        float4 v = *(const float4*)(rp + lane*4 + i*128);
        vals[i*4+0]=v.x; vals[i*4+1]=v.y; vals[i*4+2]=v.z; vals[i*4+3]=v.w;
        s  += v.x + v.y + v.z + v.w;
        ss += v.x*v.x + v.y*v.y + v.z*v.z + v.w*v.w;
    }
    #pragma unroll
    for (int o = 16; o; o >>= 1) {
        s  += __shfl_xor_sync(0xffffffffu, s,  o);
        ss += __shfl_xor_sync(0xffffffffu, ss, o);
    }
    float inv_w = 1.f / (float)width;
    float mu = s * inv_w;
    float var = ss * inv_w - mu * mu;
    float rr = rsqrtf(var + LN_EPS);
    float* op = out + (size_t)row * width;
    float m = 0.f;
    for (int i = 0; i < nv; i++) {
        int f = lane*4 + i*128;
        float4 gg = *(const float4*)(g + f);
        float4 bb = *(const float4*)(b + f);
        float y0 = (vals[i*4+0]-mu)*rr*gg.x + bb.x;
        float y1 = (vals[i*4+1]-mu)*rr*gg.y + bb.y;
        float y2 = (vals[i*4+2]-mu)*rr*gg.z + bb.z;
        float y3 = (vals[i*4+3]-mu)*rr*gg.w + bb.w;
        if (dogelu) {
            y0 = 0.5f*y0*(1.f+erff(y0*0.70710678118654752f));
            y1 = 0.5f*y1*(1.f+erff(y1*0.70710678118654752f));
            y2 = 0.5f*y2*(1.f+erff(y2*0.70710678118654752f));
            y3 = 0.5f*y3*(1.f+erff(y3*0.70710678118654752f));
        }
        vals[i*4+0]=y0; vals[i*4+1]=y1; vals[i*4+2]=y2; vals[i*4+3]=y3;
        m = fmaxf(fmaxf(fmaxf(fabsf(y0), fabsf(y1)), fmaxf(fabsf(y2), fabsf(y3))), m);
        *(float4*)(op + f) = make_float4(y0, y1, y2, y3);
    }
    if (q1p) {
        m = fmaxf(warp_max(m), 1e-20f);
        if (lane == 0) sap[row] = m * (1.f/127.f);
        float inv = 127.f / m;
        for (int i = 0; i < nv; i++) {
            int q1[4], q2[4];
            #pragma unroll
            for (int j = 0; j < 4; j++) quant2(vals[i*4+j], inv, q1[j], q2[j]);
            uint32_t* d1 = (uint32_t*)(q1p + (size_t)row*width) + i*32 + lane;
            uint32_t* d2 = (uint32_t*)(q2p + (size_t)row*width) + i*32 + lane;
            *d1 = pack4(q1[0],q1[1],q1[2],q1[3]);
            *d2 = pack4(q2[0],q2[1],q2[2],q2[3]);
        }
    }
}

// ---------------- fused GAT + residual-LN, warp per node ----------------
__global__ __launch_bounds__(256) void gat_ln(
    const float* __restrict__ xlr,
    const float* __restrict__ etype_emb,   // [3,4]
    const float* __restrict__ We,          // [4,512]
    const float* __restrict__ att,         // [4,128] = [512]
    const float* __restrict__ bo,          // [512]
    const float* __restrict__ lng, const float* __restrict__ lnb,
    float* __restrict__ x,
    int8_t* q1p, int8_t* q2p, float* sap,
    int dogelu_quant)
{
    int row = (blockIdx.x * blockDim.x + threadIdx.x) >> 5;
    if (row >= MROWS) return;
    const int lane = threadIdx.x & 31;
    const int b = row / NNODE, v = row % NNODE;

    float at[16], e0[16], e2[16], xrv[16];
    const float et0[4] = { etype_emb[0], etype_emb[1], etype_emb[2], etype_emb[3] };
    const float et2[4] = { etype_emb[8], etype_emb[9], etype_emb[10], etype_emb[11] };
    const float* xrow = xlr + (size_t)row * 1024;
    #pragma unroll
    for (int i = 0; i < 4; i++) {
        int f = lane*4 + i*128;
        float4 a4 = *(const float4*)(att + f);
        at[i*4+0]=a4.x; at[i*4+1]=a4.y; at[i*4+2]=a4.z; at[i*4+3]=a4.w;
        float4 w0 = *(const float4*)(We + 0*FDIM + f);
        float4 w1 = *(const float4*)(We + 1*FDIM + f);
        float4 w2 = *(const float4*)(We + 2*FDIM + f);
        float4 w3 = *(const float4*)(We + 3*FDIM + f);
        e0[i*4+0] = et0[0]*w0.x + et0[1]*w1.x + et0[2]*w2.x + et0[3]*w3.x;
        e0[i*4+1] = et0[0]*w0.y + et0[1]*w1.y + et0[2]*w2.y + et0[3]*w3.y;
        e0[i*4+2] = et0[0]*w0.z + et0[1]*w1.z + et0[2]*w2.z + et0[3]*w3.z;
        e0[i*4+3] = et0[0]*w0.w + et0[1]*w1.w + et0[2]*w2.w + et0[3]*w3.w;
        e2[i*4+0] = et2[0]*w0.x + et2[1]*w1.x + et2[2]*w2.x + et2[3]*w3.x;
        e2[i*4+1] = et2[0]*w0.y + et2[1]*w1.y + et2[2]*w2.y + et2[3]*w3.y;
        e2[i*4+2] = et2[0]*w0.z + et2[1]*w1.z + et2[2]*w2.z + et2[3]*w3.z;
        e2[i*4+3] = et2[0]*w0.w + et2[1]*w1.w + et2[2]*w2.w + et2[3]*w3.w;
        float4 xr4 = *(const float4*)(xrow + FDIM + f);
        xrv[i*4+0]=xr4.x; xrv[i*4+1]=xr4.y; xrv[i*4+2]=xr4.z; xrv[i*4+3]=xr4.w;
    }

    const int lo = (v < LMIR) ? 0 : LMIR;
    const int hi = (v < LMIR) ? (LMIR-1) : (NNODE-1);
    int   srcs[5];
    float c0[5], c2c[5], valid[5];
    srcs[0]=v-1; srcs[1]=v+1; srcs[2]=v-2; srcs[3]=v+2; srcs[4]=v;
    valid[0] = (v-1 >= lo) ? 1.f : 0.f;
    valid[1] = (v+1 <= hi) ? 1.f : 0.f;
    valid[2] = (v-2 >= lo) ? 1.f : 0.f;
    valid[3] = (v+2 <= hi) ? 1.f : 0.f;
    valid[4] = 1.f;
    c0[0]=1.f; c2c[0]=0.f;  c0[1]=1.f; c2c[1]=0.f;
    c0[2]=0.f; c2c[2]=1.f;  c0[3]=0.f; c2c[3]=1.f;
    float n0 = valid[0] + valid[1];
    float n2 = valid[2] + valid[3];
    float invn = 1.f / (n0 + n2);
    c0[4] = n0 * invn; c2c[4] = n2 * invn;
    #pragma unroll
    for (int e = 0; e < 5; e++) {
        int s = srcs[e];
        s = s < 0 ? 0 : (s > NNODE-1 ? NNODE-1 : s);
        srcs[e] = s;
    }

    float a[5][4];
    #pragma unroll
    for (int e = 0; e < 5; e++) {
        const float* xs = xlr + ((size_t)(b*NNODE) + srcs[e]) * 1024;
        float p0=0.f, p1=0.f, p2=0.f, p3=0.f;
        #pragma unroll
        for (int i = 0; i < 4; i++) {
            int f = lane*4 + i*128;
            float4 xv = *(const float4*)(xs + f);
            float mv[4] = {xv.x, xv.y, xv.z, xv.w};
            float p = 0.f;
            #pragma unroll
            for (int j = 0; j < 4; j++) {
                float mm = mv[j] + xrv[i*4+j] + c0[e]*e0[i*4+j] + c2c[e]*e2[i*4+j];
                mm = (mm > 0.f) ? mm : 0.2f*mm;
                p += mm * at[i*4+j];
            }
            if (i == 0) p0 = p; else if (i == 1) p1 = p; else if (i == 2) p2 = p; else p3 = p;
        }
        #pragma unroll
        for (int o = 16; o; o >>= 1) {
            p0 += __shfl_xor_sync(0xffffffffu, p0, o);
            p1 += __shfl_xor_sync(0xffffffffu, p1, o);
            p2 += __shfl_xor_sync(0xffffffffu, p2, o);
            p3 += __shfl_xor_sync(0xffffffffu, p3, o);
        }
        a[e][0] = (valid[e] > 0.f) ? p0 : -1e30f;
        a[e][1] = (valid[e] > 0.f) ? p1 : -1e30f;
        a[e][2] = (valid[e] > 0.f) ? p2 : -1e30f;
        a[e][3] = (valid[e] > 0.f) ? p3 : -1e30f;
    }
    #pragma unroll
    for (int h = 0; h < 4; h++) {
        float amax = a[0][h];
        #pragma unroll
        for (int e = 1; e < 5; e++) amax = fmaxf(amax, a[e][h]);
        float den = 0.f;
        #pragma unroll
        for (int e = 0; e < 5; e++) { a[e][h] = expf(a[e][h] - amax); den += a[e][h]; }
        float invd = 1.f / den;
        #pragma unroll
        for (int e = 0; e < 5; e++) a[e][h] *= invd;
    }

    float vals[16];
    float* xp = x + (size_t)row * FDIM;
    #pragma unroll
    for (int i = 0; i < 4; i++) {
        int f = lane*4 + i*128;
        float4 bv = *(const float4*)(bo + f);
        float4 xv = *(const float4*)(xp + f);
        vals[i*4+0] = bv.x + xv.x; vals[i*4+1] = bv.y + xv.y;
        vals[i*4+2] = bv.z + xv.z; vals[i*4+3] = bv.w + xv.w;
    }
    #pragma unroll
    for (int e = 0; e < 5; e++) {
        const float* xs = xlr + ((size_t)(b*NNODE) + srcs[e]) * 1024;
        #pragma unroll
        for (int i = 0; i < 4; i++) {
            int f = lane*4 + i*128;
            float4 xv = *(const float4*)(xs + f);
            float al = a[e][i];
            vals[i*4+0] += al * xv.x; vals[i*4+1] += al * xv.y;
            vals[i*4+2] += al * xv.z; vals[i*4+3] += al * xv.w;
        }
    }
    float s = 0.f, ss = 0.f;
    #pragma unroll
    for (int j = 0; j < 16; j++) { s += vals[j]; ss += vals[j]*vals[j]; }
    #pragma unroll
    for (int o = 16; o; o >>= 1) {
        s  += __shfl_xor_sync(0xffffffffu, s,  o);
        ss += __shfl_xor_sync(0xffffffffu, ss, o);
    }
    float mu = s * (1.f/FDIM);
    float var = ss * (1.f/FDIM) - mu*mu;
    float rr = rsqrtf(var + LN_EPS);
    float m = 0.f;
    #pragma unroll
    for (int i = 0; i < 4; i++) {
        int f = lane*4 + i*128;
        float4 gg = *(const float4*)(lng + f);
        float4 bb = *(const float4*)(lnb + f);
        float y0 = (vals[i*4+0]-mu)*rr*gg.x + bb.x;
        float y1 = (vals[i*4+1]-mu)*rr*gg.y + bb.y;
        float y2 = (vals[i*4+2]-mu)*rr*gg.z + bb.z;
        float y3 = (vals[i*4+3]-mu)*rr*gg.w + bb.w;
        if (dogelu_quant) {
            y0 = 0.5f*y0*(1.f+erff(y0*0.70710678118654752f));
            y1 = 0.5f*y1*(1.f+erff(y1*0.70710678118654752f));
            y2 = 0.5f*y2*(1.f+erff(y2*0.70710678118654752f));
            y3 = 0.5f*y3*(1.f+erff(y3*0.70710678118654752f));
        }
        vals[i*4+0]=y0; vals[i*4+1]=y1; vals[i*4+2]=y2; vals[i*4+3]=y3;
        m = fmaxf(fmaxf(fmaxf(fabsf(y0), fabsf(y1)), fmaxf(fabsf(y2), fabsf(y3))), m);
        *(float4*)(xp + f) = make_float4(y0, y1, y2, y3);
    }
    if (dogelu_quant) {
        m = fmaxf(warp_max(m), 1e-20f);
        if (lane == 0) sap[row] = m * (1.f/127.f);
        float inv = 127.f / m;
        #pragma unroll
        for (int i = 0; i < 4; i++) {
            int q1[4], q2[4];
            #pragma unroll
            for (int j = 0; j < 4; j++) quant2(vals[i*4+j], inv, q1[j], q2[j]);
            uint32_t* d1 = (uint32_t*)(q1p + (size_t)row*FDIM) + i*32 + lane;
            uint32_t* d2 = (uint32_t*)(q2p + (size_t)row*FDIM) + i*32 + lane;
            *d1 = pack4(q1[0],q1[1],q1[2],q1[3]);
            *d2 = pack4(q2[0],q2[1],q2[2],q2[3]);
        }
    }
}

// ---------------- mean/max pool ----------------
__global__ void pool(const float* __restrict__ x, float* __restrict__ pooled) {
    int b = blockIdx.x;
    int f = threadIdx.x;
    const float* xp = x + (size_t)b * NNODE * FDIM + f;
    float s = 0.f, mx = -3.4e38f;
    #pragma unroll 4
    for (int v = 0; v < NNODE; v++) {
        float val = xp[(size_t)v * FDIM];
        s += val;
        mx = fmaxf(mx, val);
    }
    pooled[(size_t)b*2*FDIM + f]        = s * (1.f/NNODE);
    pooled[(size_t)b*2*FDIM + FDIM + f] = mx;
}

// ---------------- head GEMM (tiny, fp32) ----------------
__global__ __launch_bounds__(128) void gemm_out(
    const float* __restrict__ A, const float* __restrict__ Bw,
    const float* __restrict__ bias, float* __restrict__ C)
{
    __shared__ float As[8][1024];
    const int r0 = blockIdx.x * 8;
    const int tid = threadIdx.x;
    for (int i4 = tid; i4 < 8*1024/4; i4 += 128)
        *(float4*)(&As[0][0] + (size_t)i4*4) = *(const float4*)(A + (size_t)r0*1024 + (size_t)i4*4);
    __syncthreads();
    float acc[8];
    #pragma unroll
    for (int r = 0; r < 8; r++) acc[r] = 0.f;
    #pragma unroll 4
    for (int k = 0; k < 1024; k++) {
        float bv = Bw[(size_t)k*128 + tid];
        #pragma unroll
        for (int r = 0; r < 8; r++) acc[r] += As[r][k] * bv;
    }
    float bi = bias[tid];
    #pragma unroll
    for (int r = 0; r < 8; r++)
        C[(size_t)(r0 + r)*128 + tid] = acc[r] + bi;
}

// ---------------- launch ----------------
extern "C" void kernel_launch(void* const* d_in, const int* in_sizes, int n_in,
                              void* d_out, int out_size) {
    const float* mirna  = (const float*)d_in[0];
    const float* target = (const float*)d_in[1];
    const float* ntype  = (const float*)d_in[2];
    const float* etype  = (const float*)d_in[3];
    const float* in_W   = (const float*)d_in[4];
    const float* in_b   = (const float*)d_in[5];
    const float* in_lng = (const float*)d_in[6];
    const float* in_lnb = (const float*)d_in[7];
    const float* Wl     = (const float*)d_in[8];
    const float* bl     = (const float*)d_in[9];
    const float* Wr     = (const float*)d_in[10];
    const float* br     = (const float*)d_in[11];
    const float* We     = (const float*)d_in[12];
    const float* attw   = (const float*)d_in[13];
    const float* bo     = (const float*)d_in[14];
    const float* lng    = (const float*)d_in[15];
    const float* lnb    = (const float*)d_in[16];
    const float* outW   = (const float*)d_in[17];
    const float* outb   = (const float*)d_in[18];
    const float* olng   = (const float*)d_in[19];
    const float* olnb   = (const float*)d_in[20];
    float* out = (float*)d_out;

    float *xp, *xlrp, *hp, *poolp, *op, *bcatp, *asp, *wisp, *wcsp;
    int8_t *aq1p, *aq2p, *wiq1p, *wiq2p, *wcq1p, *wcq2p;
    cudaGetSymbolAddress((void**)&aq1p,  g_aq1);
    cudaGetSymbolAddress((void**)&aq2p,  g_aq2);
    cudaGetSymbolAddress((void**)&asp,   g_as);
    cudaGetSymbolAddress((void**)&wiq1p, g_wiq1);
    cudaGetSymbolAddress((void**)&wiq2p, g_wiq2);
    cudaGetSymbolAddress((void**)&wisp,  g_wis);
    cudaGetSymbolAddress((void**)&wcq1p, g_wcq1);
    cudaGetSymbolAddress((void**)&wcq2p, g_wcq2);
    cudaGetSymbolAddress((void**)&wcsp,  g_wcs);
    cudaGetSymbolAddress((void**)&bcatp, g_bcat);
    cudaGetSymbolAddress((void**)&xp,    g_x);
    cudaGetSymbolAddress((void**)&xlrp,  g_xlr);
    cudaGetSymbolAddress((void**)&hp,    g_h);
    cudaGetSymbolAddress((void**)&poolp, g_pool);
    cudaGetSymbolAddress((void**)&op,    g_o);

    cudaFuncSetAttribute(gemm_i8, cudaFuncAttributeMaxDynamicSharedMemorySize, GEMM_SMEM);

    prep_weights<<<(2560*32 + 255)/256, 256>>>(in_W, Wl, Wr, bl, br);
    build_x0<<<(MROWS*32 + 255)/256, 256>>>(mirna, target, ntype);

    // input projection (M=81920, N=512, K=256)
    gemm_i8<<<dim3(FDIM/BN, MROWS/BM), 256, GEMM_SMEM>>>(
        aq1p, aq2p, asp, wiq1p, wiq2p, wisp, in_b, hp, NDIM, FDIM);
    ln_gelu<<<(MROWS*32 + 255)/256, 256>>>(hp, xp, aq1p, aq2p, asp,
                                           in_lng, in_lnb, MROWS, FDIM, 1);

    // GAT layers: fused [Wl|Wr] int8 GEMM + fused gat+resid_ln
    for (int i = 0; i < 2; i++) {
        gemm_i8<<<dim3(1024/BN, MROWS/BM), 256, GEMM_SMEM>>>(
            aq1p, aq2p, asp,
            wcq1p + (size_t)i*1024*FDIM, wcq2p + (size_t)i*1024*FDIM, wcsp + (size_t)i*1024,
            bcatp + (size_t)i*1024, xlrp, FDIM, 1024);
        gat_ln<<<(MROWS*32 + 255)/256, 256>>>(
            xlrp, etype,
            We + (size_t)i*HEADS*FDIM, attw + (size_t)i*HEADS*CDIM,
            bo + (size_t)i*FDIM, lng + (size_t)i*FDIM, lnb + (size_t)i*FDIM,
            xp, aq1p, aq2p, asp, (i == 0) ? 1 : 0);
    }

    // pool + head
    pool<<<BSZ, FDIM>>>(xp, poolp);
    gemm_out<<<BSZ/8, 128>>>(poolp, outW, outb, op);
    ln_gelu<<<(BSZ*32 + 255)/256, 256>>>(op, out, (int8_t*)nullptr, (int8_t*)nullptr, (float*)nullptr,
                                         olng, olnb, BSZ, OUTD, 1);
}